// round 5
// baseline (speedup 1.0000x reference)
#include <cuda_runtime.h>
#include <cuda_bf16.h>
#include <cstdint>

#define BATCH   4096
#define NB      64
#define IN_DIM  256
#define NTOT    4096
#define DT_C    0.05f
#define TAU_EPS 1e-6f

// bf16 tile row pitch: 72 elems = 144 bytes (odd 16B-groups -> conflict-free ldmatrix)
#define PITCH   144

// ---------------- SMEM layout (byte offsets) ----------------
#define A0_OFF  0                       // 128 x 64 bf16 (y_prev | u chunk)
#define A1_OFF  18432                   // 128 x 64 bf16 (y_cur)
#define W0_OFF  36864                   // W_fwd[j-1] | W_in chunk
#define W1_OFF  46080                   // W_rec[j]
#define W2_OFF  55296                   // E_l[j]
#define W3_OFF  64512                   // E_l_r[j]
#define BR_OFF  73728                   // br        (64 f32)
#define BF_OFF  (BR_OFF + 256)          // bf | bi   (64 f32)
#define IT_OFF  (BF_OFF + 256)          // 1/tau     (64 f32)
#define SMEM_TOTAL (IT_OFF + 256)       // 74496 B -> 3 CTAs/SM

// ---------------------------------------------------------------------------
// helpers
// ---------------------------------------------------------------------------
__device__ __forceinline__ uint32_t smem_u32(const void* p) {
    uint32_t a;
    asm("{ .reg .u64 t; cvta.to.shared.u64 t, %1; cvt.u32.u64 %0, t; }"
        : "=r"(a) : "l"(p));
    return a;
}
__device__ __forceinline__ float tanh_fast(float x) {
    float r; asm("tanh.approx.f32 %0, %1;" : "=f"(r) : "f"(x)); return r;
}
__device__ __forceinline__ uint32_t bf2(float lo, float hi) {
    uint32_t r;
    asm("cvt.rn.bf16x2.f32 %0, %1, %2;" : "=r"(r) : "f"(hi), "f"(lo));
    return r;
}
__device__ __forceinline__ float2 ubf2(uint32_t v) {
    __nv_bfloat162 b = *reinterpret_cast<__nv_bfloat162*>(&v);
    return __bfloat1622float2(b);
}

#define LDM4(r, addr) \
    asm volatile("ldmatrix.sync.aligned.m8n8.x4.shared.b16 {%0,%1,%2,%3}, [%4];" \
        : "=r"((r)[0]), "=r"((r)[1]), "=r"((r)[2]), "=r"((r)[3]) : "r"(addr))

__device__ __forceinline__ void mma16816(float* c, const uint32_t* a,
                                         uint32_t b0, uint32_t b1) {
    asm volatile(
        "mma.sync.aligned.m16n8k16.row.col.f32.bf16.bf16.f32 "
        "{%0,%1,%2,%3}, {%4,%5,%6,%7}, {%8,%9}, {%0,%1,%2,%3};"
        : "+f"(c[0]), "+f"(c[1]), "+f"(c[2]), "+f"(c[3])
        : "r"(a[0]), "r"(a[1]), "r"(a[2]), "r"(a[3]), "r"(b0), "r"(b1));
}

// Warp computes C[32 x 64] += A_smem[32 x 64] * W_smem[64 x 64]^T
__device__ __forceinline__ void gemm32x64(uint32_t abase, uint32_t wbase,
                                          float acc[16][4], int lane, int warpM)
{
    uint32_t pa = abase + (uint32_t)((warpM + (lane & 7) + ((lane >> 3) & 1) * 8) * PITCH
                                     + ((lane >> 4) * 8) * 2);
    uint32_t pb = wbase + (uint32_t)((((lane & 7) + ((lane >> 4) & 1) * 8)) * PITCH
                                     + (((lane >> 3) & 1) * 8) * 2);
#pragma unroll
    for (int ks = 0; ks < 4; ks++) {
        uint32_t a0[4], a1[4];
        LDM4(a0, pa + ks * 32);
        LDM4(a1, pa + 16 * PITCH + ks * 32);
#pragma unroll
        for (int np = 0; np < 4; np++) {
            uint32_t b[4];
            LDM4(b, pb + np * 16 * PITCH + ks * 32);
            mma16816(acc[np * 2 + 0],     a0, b[0], b[1]);
            mma16816(acc[np * 2 + 1],     a0, b[2], b[3]);
            mma16816(acc[8 + np * 2 + 0], a1, b[0], b[1]);
            mma16816(acc[8 + np * 2 + 1], a1, b[2], b[3]);
        }
    }
}

// Warp computes C[32 x 64] += A_regs[32 x 64] * W_smem[64 x 64]^T
// A given as packed bf16x2 fragments: lo[mt][nt] rows (m..), hi = rows+8.
__device__ __forceinline__ void gemm32x64_reg(uint32_t wbase,
                                              const uint32_t lo[2][8],
                                              const uint32_t hi[2][8],
                                              float acc[16][4], int lane)
{
    uint32_t pb = wbase + (uint32_t)((((lane & 7) + ((lane >> 4) & 1) * 8)) * PITCH
                                     + (((lane >> 3) & 1) * 8) * 2);
#pragma unroll
    for (int ks = 0; ks < 4; ks++) {
#pragma unroll
        for (int np = 0; np < 4; np++) {
            uint32_t b[4];
            LDM4(b, pb + np * 16 * PITCH + ks * 32);
#pragma unroll
            for (int mt = 0; mt < 2; mt++) {
                uint32_t a[4] = { lo[mt][2 * ks], hi[mt][2 * ks],
                                  lo[mt][2 * ks + 1], hi[mt][2 * ks + 1] };
                mma16816(acc[mt * 8 + np * 2 + 0], a, b[0], b[1]);
                mma16816(acc[mt * 8 + np * 2 + 1], a, b[2], b[3]);
            }
        }
    }
}

// tanh(acc + bias) -> packed bf16x2 fragments in registers
__device__ __forceinline__ void pack_tanh(const float acc[16][4], const float* bias,
                                          uint32_t lo[2][8], uint32_t hi[2][8],
                                          int lane)
{
    const int nb = (lane & 3) * 2;
#pragma unroll
    for (int mt = 0; mt < 2; mt++)
#pragma unroll
        for (int nt = 0; nt < 8; nt++) {
            const float* c = acc[mt * 8 + nt];
            float b0 = bias[nt * 8 + nb], b1 = bias[nt * 8 + nb + 1];
            lo[mt][nt] = bf2(tanh_fast(c[0] + b0), tanh_fast(c[1] + b1));
            hi[mt][nt] = bf2(tanh_fast(c[2] + b0), tanh_fast(c[3] + b1));
        }
}

__device__ __forceinline__ void zero_acc(float acc[16][4]) {
#pragma unroll
    for (int i = 0; i < 16; i++)
#pragma unroll
        for (int q = 0; q < 4; q++) acc[i][q] = 0.f;
}

// stage a 128x64 fp32 gmem tile (row stride = srcPitch) as bf16 into smem tile
__device__ __forceinline__ void stage128(char* dst, const float* __restrict__ src,
                                         int srcPitch, int t)
{
#pragma unroll
    for (int i = 0; i < 16; i++) {
        int idx = t + i * 128;
        int r = idx >> 4, c4 = idx & 15;
        float4 v = *(const float4*)&src[r * srcPitch + c4 * 4];
        *(uint2*)(dst + r * PITCH + c4 * 8) = make_uint2(bf2(v.x, v.y), bf2(v.z, v.w));
    }
}
// stage a 64x64 fp32 weight tile as bf16
__device__ __forceinline__ void stage64(char* dst, const float* __restrict__ src,
                                        int srcPitch, int t)
{
#pragma unroll
    for (int i = 0; i < 8; i++) {
        int idx = t + i * 128;
        int o = idx >> 4, c4 = idx & 15;
        float4 v = *(const float4*)&src[o * srcPitch + c4 * 4];
        *(uint2*)(dst + o * PITCH + c4 * 8) = make_uint2(bf2(v.x, v.y), bf2(v.z, v.w));
    }
}

// ---------------------------------------------------------------------------
// Single fused kernel. grid (32 batch tiles, 64 blocks j), 128 threads.
// ---------------------------------------------------------------------------
__global__ void __launch_bounds__(128, 3) ltc_main(
    const float* __restrict__ y,
    const float* __restrict__ u,
    const float* __restrict__ tau_raw,
    const float* __restrict__ Wi,  const float* __restrict__ bi,
    const float* __restrict__ Wf,  const float* __restrict__ bfw,
    const float* __restrict__ Wr,  const float* __restrict__ brw,
    const float* __restrict__ El,  const float* __restrict__ Elr,
    float* __restrict__ out)
{
    extern __shared__ char sm[];
    const int t     = threadIdx.x;
    const int lane  = t & 31;
    const int warpM = (t >> 5) * 32;
    const int bt    = blockIdx.x;
    const int j     = blockIdx.y;
    const int row0  = bt * 128;

    float* s_br = (float*)(sm + BR_OFF);
    float* s_bf = (float*)(sm + BF_OFF);
    float* s_it = (float*)(sm + IT_OFF);
    const uint32_t smb = smem_u32(sm);

    // ---------------- Stage ----------------
    stage128(sm + A1_OFF, y + (size_t)row0 * NTOT + j * 64, NTOT, t);
    if (j > 0) {
        stage128(sm + A0_OFF, y + (size_t)row0 * NTOT + (j - 1) * 64, NTOT, t);
        stage64(sm + W0_OFF, Wf + (j - 1) * 4096, 64, t);
    }
    stage64(sm + W1_OFF, Wr  + j * 4096, 64, t);
    stage64(sm + W2_OFF, El  + j * 4096, 64, t);
    stage64(sm + W3_OFF, Elr + j * 4096, 64, t);
    if (t < 64) {
        s_br[t] = brw[j * 64 + t];
        s_bf[t] = (j > 0) ? bfw[(j - 1) * 64 + t] : bi[t];
        float x  = tau_raw[j * 64 + t];
        float sp = (x > 20.f) ? x : log1pf(expf(x));
        s_it[t]  = 1.0f / (sp + TAU_EPS);
    }
    __syncthreads();

    float acc[16][4];
    uint32_t nr_lo[2][8], nr_hi[2][8];   // net_rec packed bf16x2 fragments
    uint32_t no_lo[2][8], no_hi[2][8];   // net_out packed bf16x2 fragments

    // ---------------- Phase 1a: net_rec = tanh(y_cur @ Wr^T + br) ----------
    zero_acc(acc);
    gemm32x64(smb + A1_OFF, smb + W1_OFF, acc, lane, warpM);
    pack_tanh(acc, s_br, nr_lo, nr_hi, lane);

    // ---------------- Phase 1b: net_out ------------------------------------
    zero_acc(acc);
    if (j > 0) {
        gemm32x64(smb + A0_OFF, smb + W0_OFF, acc, lane, warpM);
    } else {
        // net0 = u_t @ W_in^T over K=256 in 4 staged chunks (block-uniform)
        for (int kc = 0; kc < 4; kc++) {
            __syncthreads();
            stage128(sm + A0_OFF, u + (size_t)row0 * IN_DIM + kc * 64, IN_DIM, t);
            stage64(sm + W0_OFF, Wi + kc * 64, IN_DIM, t);
            __syncthreads();
            gemm32x64(smb + A0_OFF, smb + W0_OFF, acc, lane, warpM);
        }
    }
    pack_tanh(acc, s_bf, no_lo, no_hi, lane);

    // ---------------- Phase 2: drive = net_out@El^T + net_rec@Elr^T --------
    zero_acc(acc);
    gemm32x64_reg(smb + W2_OFF, no_lo, no_hi, acc, lane);
    gemm32x64_reg(smb + W3_OFF, nr_lo, nr_hi, acc, lane);

    // ---------------- Epilogue: direct fragment-wise combine + store -------
    {
        const int gm = warpM + (lane >> 2);
        const int nb = (lane & 3) * 2;
#pragma unroll
        for (int mt = 0; mt < 2; mt++)
#pragma unroll
            for (int nt = 0; nt < 8; nt++) {
                int n    = nt * 8 + nb;
                int gcol = j * 64 + n;
                float it0 = s_it[n], it1 = s_it[n + 1];
                float2 no0 = ubf2(no_lo[mt][nt]), no1 = ubf2(no_hi[mt][nt]);
                float2 nr0 = ubf2(nr_lo[mt][nt]), nr1 = ubf2(nr_hi[mt][nt]);
                const float* c = acc[mt * 8 + nt];
                size_t m0 = (size_t)(row0 + gm + mt * 16);
                float2 ya = *(const float2*)&y[m0 * NTOT + gcol];
                float2 yc = *(const float2*)&y[(m0 + 8) * NTOT + gcol];
                float2 o0, o1;
                o0.x = (ya.x + DT_C * c[0]) /
                       (1.f + DT_C * (it0 + fabsf(no0.x) + fabsf(nr0.x)));
                o0.y = (ya.y + DT_C * c[1]) /
                       (1.f + DT_C * (it1 + fabsf(no0.y) + fabsf(nr0.y)));
                o1.x = (yc.x + DT_C * c[2]) /
                       (1.f + DT_C * (it0 + fabsf(no1.x) + fabsf(nr1.x)));
                o1.y = (yc.y + DT_C * c[3]) /
                       (1.f + DT_C * (it1 + fabsf(no1.y) + fabsf(nr1.y)));
                *(float2*)&out[m0 * NTOT + gcol] = o0;
                *(float2*)&out[(m0 + 8) * NTOT + gcol] = o1;
            }
    }
}

// ---------------------------------------------------------------------------
extern "C" void kernel_launch(void* const* d_in, const int* in_sizes, int n_in,
                              void* d_out, int out_size) {
    const float* y   = (const float*)d_in[0];
    const float* u_t = (const float*)d_in[1];
    const float* tau = (const float*)d_in[2];
    const float* Wi  = (const float*)d_in[3];
    const float* bi  = (const float*)d_in[4];
    const float* Wf  = (const float*)d_in[5];
    const float* bfw = (const float*)d_in[6];
    const float* Wr  = (const float*)d_in[7];
    const float* brw = (const float*)d_in[8];
    const float* El  = (const float*)d_in[9];
    const float* Elr = (const float*)d_in[10];
    float* out = (float*)d_out;

    cudaFuncSetAttribute(ltc_main, cudaFuncAttributeMaxDynamicSharedMemorySize,
                         SMEM_TOTAL);

    ltc_main<<<dim3(BATCH / 128, NB), 128, SMEM_TOTAL>>>(
        y, u_t, tau, Wi, bi, Wf, bfw, Wr, brw, El, Elr, out);
}